// round 13
// baseline (speedup 1.0000x reference)
#include <cuda_runtime.h>
#include <cuda_fp16.h>
#include <math.h>

// ---------------------------------------------------------------------------
// Problem constants
// ---------------------------------------------------------------------------
#define B_    8
#define CIN   256
#define MID   128
#define Hh    128
#define Ww    256
#define Kk    19
#define HW    (Hh*Ww)          // 32768
#define EPSBN 1e-5f

// ---------------------------------------------------------------------------
// Scratch (device globals: allocation-free)
// ---------------------------------------------------------------------------
__device__ __half g_w1h[9 * MID * CIN];              // fp16 [(dy*8+cc)*3+dx][mid][32]
__device__ __half g_w2h[80 * MID];                   // fp16 w2 padded to 80 rows
__device__ float  g_g[(size_t)B_ * Kk * HW * 4];     // guidance [b][k][hw][4]

// ---------------------------------------------------------------------------
// Helpers
// ---------------------------------------------------------------------------
static __device__ __forceinline__ unsigned smem_u32(const void* p) {
    unsigned r;
    asm("{ .reg .u64 t; cvta.to.shared.u64 t, %1; cvt.u32.u64 %0, t; }"
        : "=r"(r) : "l"(p));
    return r;
}

static __device__ __forceinline__ void cp16(unsigned saddr, const void* gptr) {
    asm volatile("cp.async.cg.shared.global [%0], [%1], 16;"
                 :: "r"(saddr), "l"(gptr));
}

static __device__ __forceinline__ void ldsm4(unsigned* r, unsigned addr) {
    asm volatile("ldmatrix.sync.aligned.m8n8.x4.shared.b16 {%0,%1,%2,%3}, [%4];"
        : "=r"(r[0]), "=r"(r[1]), "=r"(r[2]), "=r"(r[3]) : "r"(addr));
}

static __device__ __forceinline__ void mma16816(float* c, const unsigned* a,
                                                const unsigned* b) {
    asm volatile(
        "mma.sync.aligned.m16n8k16.row.col.f32.f16.f16.f32 "
        "{%0,%1,%2,%3}, {%4,%5,%6,%7}, {%8,%9}, {%0,%1,%2,%3};"
        : "+f"(c[0]), "+f"(c[1]), "+f"(c[2]), "+f"(c[3])
        : "r"(a[0]), "r"(a[1]), "r"(a[2]), "r"(a[3]), "r"(b[0]), "r"(b[1]));
}

// swizzled offset within a 64B-row tile
static __device__ __forceinline__ unsigned swz64(int row, int ch) {
    return row * 64 + ((ch ^ ((row >> 1) & 3)) << 4);
}
// swizzled offset within a 256B-row tile
static __device__ __forceinline__ unsigned swz256(int row, int ch) {
    return row * 256 + ((ch & 8) << 4) + (((ch & 7) ^ (row & 7)) << 4);
}

// ---------------------------------------------------------------------------
// Kernel T2: both weight preps in one launch.
// ---------------------------------------------------------------------------
#define W1ELEMS (9 * MID * CIN)
__global__ __launch_bounds__(256) void prep_weights_kernel(
    const float* __restrict__ w1, const float* __restrict__ w2)
{
    int idx = blockIdx.x * 256 + threadIdx.x;
    if (idx < W1ELEMS) {
        int cw = idx & 31;
        int m  = (idx >> 5) & 127;
        int rest = idx >> 12;
        int dx = rest % 3, q = rest / 3;
        int cc = q & 7, dy = q >> 3;
        int ci = cc * 32 + cw;
        g_w1h[idx] = __float2half_rn(w1[(((size_t)m * CIN + ci) * 3 + dy) * 3 + dx]);
    } else if (idx < W1ELEMS + 80 * MID) {
        int j = idx - W1ELEMS;
        int n = j >> 7, m = j & 127;
        float v = (n < 76) ? w2[n * MID + m] : 0.f;
        g_w2h[j] = __float2half_rn(v);
    }
}

// ---------------------------------------------------------------------------
// Kernel G: conv3x3 fp16 mma implicit GEMM, 256 thr / 8 warps, 2 CTAs/SM,
// with FUSED NCHW->fp16 transpose in the A-load path (no transpose kernel):
// per A-granule, 8 coalesced LDG.32 from fp32 feats + cvt + 1 swizzled STS.128.
// Per CTA one (b, h, half-row): M=128 px, N=128 mid, K=2304.
// FUSED epilogue: BN+ReLU -> smem x -> conv1x1 mma -> softmax -> g_g.
// ---------------------------------------------------------------------------
#define A_ST   8320                  // 130*64
#define B_ST   24576                 // 3*128*64
#define STG    (A_ST + B_ST)         // 32896
#define NSTG   3
#define CSMEM  (NSTG * STG)          // 98688; 2 CTAs = 197376
#define SX_OFF 0
#define SW2_OFF 32768

__global__ void __launch_bounds__(256, 2) conv3x3_fused_kernel(
    const float* __restrict__ feats,
    const float* __restrict__ gamma, const float* __restrict__ beta,
    const float* __restrict__ mean,  const float* __restrict__ var,
    const float* __restrict__ b2)
{
    extern __shared__ __align__(1024) unsigned char smem_raw[];
    const unsigned sbase = smem_u32(smem_raw);
    const int tid = threadIdx.x;
    const int L = tid & 31, wid = tid >> 5;
    const int h = blockIdx.x >> 1;
    const int wseg = (blockIdx.x & 1) * 128;
    const int b = blockIdx.y;
    const int p0w = (wid >> 2) * 64;
    const int n0w = (wid & 3) * 32;

    const int aL = L & 15, aH = L >> 4;
    const int bR = ((L >> 4) << 3) + (L & 7), bH = (L >> 3) & 1;

    auto issue_loads = [&](int t, int buf) {
        const int dy = t >> 3, cc = t & 7;
        const unsigned Ab = sbase + buf * STG;
        const unsigned Bb = Ab + A_ST;
        // B: weights via cp.async (3 dx x 128 rows x 4 chunks)
        const __half* bsrc = g_w1h + (size_t)((dy * 8 + cc) * 3) * MID * 32;
#pragma unroll
        for (int i = 0; i < 6; i++) {
            int g = tid + i * 256;
            int dxi = g >> 9, row = (g >> 2) & 127, c = g & 3;
            cp16(Bb + dxi * 8192 + swz64(row, c),
                 bsrc + (size_t)dxi * MID * 32 + row * 32 + c * 8);
        }
        asm volatile("cp.async.commit_group;");
        // A: fused NCHW fp32 -> fp16 K-major (520 granules of 8 cin x 1 px)
        const int ih = h + dy - 1;
        const bool hok = ((unsigned)ih < (unsigned)Hh);
#pragma unroll
        for (int i = 0; i < 3; i++) {
            int g = tid + i * 256;
            if (g < 520) {
                int row = g >> 2, c = g & 3;
                int iw = wseg + row - 1;
                bool valid = hok && ((unsigned)iw < (unsigned)Ww);
                const float* fs = feats +
                    (((size_t)b * CIN + cc * 32 + c * 8) * Hh + ih) * Ww + iw;
                float v[8];
#pragma unroll
                for (int j = 0; j < 8; j++)
                    v[j] = valid ? fs[(size_t)j * HW] : 0.f;
                __half2 pk[4];
#pragma unroll
                for (int q = 0; q < 4; q++)
                    pk[q] = __floats2half2_rn(v[2 * q], v[2 * q + 1]);
                *(float4*)(smem_raw + buf * STG + swz64(row, c)) = *(float4*)pk;
            }
        }
    };

    float acc[4][4][4];
#pragma unroll
    for (int mi = 0; mi < 4; mi++)
#pragma unroll
        for (int ni = 0; ni < 4; ni++)
#pragma unroll
            for (int q = 0; q < 4; q++) acc[mi][ni][q] = 0.f;

    issue_loads(0, 0);
    issue_loads(1, 1);

    int buf = 0;
    for (int t = 0; t < 24; t++) {
        if (t < 23) asm volatile("cp.async.wait_group 1;");
        else        asm volatile("cp.async.wait_group 0;");
        __syncthreads();
        if (t < 22) {
            int nb = buf + 2; if (nb >= NSTG) nb -= NSTG;
            issue_loads(t + 2, nb);
        }
        const unsigned Ab = sbase + buf * STG;
        const unsigned Bb = Ab + A_ST;
#pragma unroll
        for (int dx = 0; dx < 3; dx++) {
#pragma unroll
            for (int kk = 0; kk < 2; kk++) {
                unsigned a[4][4], bf[2][4];
#pragma unroll
                for (int mi = 0; mi < 4; mi++) {
                    int row = p0w + mi * 16 + aL + dx;
                    ldsm4(a[mi], Ab + swz64(row, 2 * kk + aH));
                }
#pragma unroll
                for (int jj = 0; jj < 2; jj++) {
                    int row = n0w + jj * 16 + bR;
                    ldsm4(bf[jj], Bb + dx * 8192 + swz64(row, 2 * kk + bH));
                }
#pragma unroll
                for (int mi = 0; mi < 4; mi++)
#pragma unroll
                    for (int ni = 0; ni < 4; ni++)
                        mma16816(acc[mi][ni], a[mi],
                                 &bf[ni >> 1][(ni & 1) << 1]);
            }
        }
        buf++; if (buf >= NSTG) buf = 0;
    }
    __syncthreads();

    // ---- load w2 into smem (swz256) ----
    const unsigned sw2 = sbase + SW2_OFF;
#pragma unroll
    for (int i = 0; i < 5; i++) {
        int g = tid + i * 256;
        if (g < 1280) {
            int row = g >> 4, c = g & 15;
            cp16(sw2 + swz256(row, c), g_w2h + (size_t)row * MID + c * 8);
        }
    }
    asm volatile("cp.async.commit_group;");

    // ---- BN + ReLU, store x fp16 into smem ----
    const int midb = n0w + ((L & 3) << 1);
    {
        float iv0[4], iv1[4], bb0[4], bb1[4];
#pragma unroll
        for (int ni = 0; ni < 4; ni++) {
            int m0 = midb + ni * 8;
            iv0[ni] = gamma[m0]     * rsqrtf(var[m0]     + EPSBN);
            iv1[ni] = gamma[m0 + 1] * rsqrtf(var[m0 + 1] + EPSBN);
            bb0[ni] = beta[m0]     - mean[m0]     * iv0[ni];
            bb1[ni] = beta[m0 + 1] - mean[m0 + 1] * iv1[ni];
        }
        const int chb = (n0w >> 3);
        const int boff = (L & 3) * 4;
#pragma unroll
        for (int mi = 0; mi < 4; mi++) {
            int p0 = p0w + mi * 16 + (L >> 2);
#pragma unroll
            for (int ni = 0; ni < 4; ni++) {
                float u0 = fmaxf(fmaf(acc[mi][ni][0], iv0[ni], bb0[ni]), 0.f);
                float u1 = fmaxf(fmaf(acc[mi][ni][1], iv1[ni], bb1[ni]), 0.f);
                float u2 = fmaxf(fmaf(acc[mi][ni][2], iv0[ni], bb0[ni]), 0.f);
                float u3 = fmaxf(fmaf(acc[mi][ni][3], iv1[ni], bb1[ni]), 0.f);
                *(__half2*)(smem_raw + SX_OFF + swz256(p0, chb + ni) + boff)
                    = __floats2half2_rn(u0, u1);
                *(__half2*)(smem_raw + SX_OFF + swz256(p0 + 8, chb + ni) + boff)
                    = __floats2half2_rn(u2, u3);
            }
        }
    }
    asm volatile("cp.async.wait_group 0;");
    __syncthreads();

    // ---- conv1x1: per-warp 16px x 80n x 128k fp16 mma ----
    const unsigned sx = sbase + SX_OFF;
    const int pwm = wid * 16;
    float a1[10][4];
#pragma unroll
    for (int ni = 0; ni < 10; ni++)
#pragma unroll
        for (int q = 0; q < 4; q++) a1[ni][q] = 0.f;

#pragma unroll
    for (int kk = 0; kk < 8; kk++) {
        unsigned av[4], bf[5][4];
        {
            int row = pwm + (L & 15);
            ldsm4(av, sx + swz256(row, 2 * kk + (L >> 4)));
        }
#pragma unroll
        for (int jj = 0; jj < 5; jj++) {
            int row = jj * 16 + ((L >> 4) << 3) + (L & 7);
            ldsm4(bf[jj], sw2 + swz256(row, 2 * kk + ((L >> 3) & 1)));
        }
#pragma unroll
        for (int ni = 0; ni < 10; ni++)
            mma16816(a1[ni], av, &bf[ni >> 1][(ni & 1) << 1]);
    }

    // ---- bias + softmax over 4 dirs, write g_g ----
    const int d0 = (L & 1) * 2;
#pragma unroll
    for (int h2 = 0; h2 < 2; h2++) {
        int px = pwm + (L >> 2) + h2 * 8;
        size_t gp = (size_t)h * Ww + wseg + px;
#pragma unroll
        for (int ni = 0; ni < 10; ni++) {
            int n0 = 8 * ni + 2 * (L & 3);
            bool valid = (n0 < 76);
            float bb0 = valid ? b2[n0] : 0.f;
            float bb1 = valid ? b2[n0 + 1] : 0.f;
            float v0 = a1[ni][2 * h2]     + bb0;
            float v1 = a1[ni][2 * h2 + 1] + bb1;
            float p0v = __shfl_xor_sync(0xFFFFFFFFu, v0, 1);
            float p1v = __shfl_xor_sync(0xFFFFFFFFu, v1, 1);
            float mx = fmaxf(fmaxf(v0, v1), fmaxf(p0v, p1v));
            float e0 = expf(v0 - mx), e1 = expf(v1 - mx);
            float ep0 = expf(p0v - mx), ep1 = expf(p1v - mx);
            float inv = 1.f / (e0 + e1 + ep0 + ep1);
            if (valid) {
                int k = n0 >> 2;
                float2 r; r.x = e0 * inv; r.y = e1 * inv;
                *(float2*)(g_g + (((size_t)b * Kk + k) * HW + gp) * 4 + d0) = r;
            }
        }
    }
}

// ---------------------------------------------------------------------------
// Kernel 3: 4 fused propagation steps; 32x32 tile + halo 4 (round-10 best).
// g cached in registers (step-invariant), 7 cells/thread.
// ---------------------------------------------------------------------------
#define TR 40
#define NCELL 7

__global__ __launch_bounds__(256) void prop_fused_kernel(
    const float* __restrict__ logits, float* __restrict__ h_out)
{
    __shared__ float sh[2][TR * TR];

    const int tid = threadIdx.x;
    const int wo = blockIdx.x * 32, ho = blockIdx.y * 32;
    const int plane = blockIdx.z;
    const float* hsrc = logits + (size_t)plane * HW;
    const float* gsrc = g_g + (size_t)plane * HW * 4;

    float4 gr[NCELL];
    int rr_[NCELL], cc_[NCELL];
    bool own[NCELL];

#pragma unroll
    for (int i = 0; i < NCELL; i++) {
        int q = tid + i * 256;
        own[i] = (q < TR * TR);
        int r = q / TR, c = q - r * TR;
        rr_[i] = r; cc_[i] = c;
        float4 gv = make_float4(0.f, 0.f, 0.f, 0.f);
        float hv = 0.f;
        if (own[i]) {
            int grow = ho + r - 4, gcol = wo + c - 4;
            bool in = ((unsigned)grow < (unsigned)Hh) &&
                      ((unsigned)gcol < (unsigned)Ww);
            if (in) {
                gv = *(const float4*)(gsrc + ((size_t)grow * Ww + gcol) * 4);
                hv = hsrc[(size_t)grow * Ww + gcol];
            }
            sh[0][q] = hv;
        }
        gr[i] = gv;
    }
    __syncthreads();

#pragma unroll
    for (int s = 1; s <= 3; s++) {
        const float* src = sh[(s - 1) & 1];
        float* dst = sh[s & 1];
#pragma unroll
        for (int i = 0; i < NCELL; i++) {
            if (!own[i]) continue;
            int r = rr_[i], c = cc_[i];
            if (r >= s && r < TR - s && c >= s && c < TR - s) {
                int id = r * TR + c;
                float hc = src[id];
                float l = src[id - 1], rt = src[id + 1];
                float u = src[id - TR], d = src[id + TR];
                float4 gv = gr[i];
                float selfw = 1.f - (gv.x + gv.y + gv.z + gv.w);
                dst[id] = selfw * hc + gv.x * l + gv.y * rt + gv.z * u + gv.w * d;
            }
        }
        __syncthreads();
    }

    const float* src = sh[1];
#pragma unroll
    for (int i = 0; i < NCELL; i++) {
        if (!own[i]) continue;
        int r = rr_[i], c = cc_[i];
        if (r >= 4 && r < TR - 4 && c >= 4 && c < TR - 4) {
            int id = r * TR + c;
            float hc = src[id];
            float l = src[id - 1], rt = src[id + 1];
            float u = src[id - TR], d = src[id + TR];
            float4 gv = gr[i];
            float selfw = 1.f - (gv.x + gv.y + gv.z + gv.w);
            float res = selfw * hc + gv.x * l + gv.y * rt + gv.z * u + gv.w * d;
            h_out[(size_t)plane * HW + (size_t)(ho + r - 4) * Ww + (wo + c - 4)] = res;
        }
    }
}

// ---------------------------------------------------------------------------
// kernel_launch
// inputs: 0 feats, 1 logits, 2 w1, 3 gamma, 4 beta, 5 mean, 6 var, 7 w2, 8 b2
// ---------------------------------------------------------------------------
extern "C" void kernel_launch(void* const* d_in, const int* in_sizes, int n_in,
                              void* d_out, int out_size)
{
    const float* feats  = (const float*)d_in[0];
    const float* logits = (const float*)d_in[1];
    const float* w1     = (const float*)d_in[2];
    const float* gamma  = (const float*)d_in[3];
    const float* beta   = (const float*)d_in[4];
    const float* mean   = (const float*)d_in[5];
    const float* var    = (const float*)d_in[6];
    const float* w2     = (const float*)d_in[7];
    const float* b2     = (const float*)d_in[8];
    float* out = (float*)d_out;

    cudaFuncSetAttribute(conv3x3_fused_kernel,
                         cudaFuncAttributeMaxDynamicSharedMemorySize, CSMEM);

    prep_weights_kernel<<<(W1ELEMS + 80 * MID + 255) / 256, 256>>>(w1, w2);
    conv3x3_fused_kernel<<<dim3(Hh * 2, B_), 256, CSMEM>>>(
        feats, gamma, beta, mean, var, b2);
    prop_fused_kernel<<<dim3(Ww / 32, Hh / 32, B_ * Kk), 256>>>(logits, out);
}

// round 14
// speedup vs baseline: 1.0473x; 1.0473x over previous
#include <cuda_runtime.h>
#include <cuda_fp16.h>
#include <math.h>

// ---------------------------------------------------------------------------
// Problem constants
// ---------------------------------------------------------------------------
#define B_    8
#define CIN   256
#define MID   128
#define Hh    128
#define Ww    256
#define Kk    19
#define HW    (Hh*Ww)          // 32768
#define EPSBN 1e-5f
#define HP    (Hh+2)           // 130
#define WP    (Ww+2)           // 258

// ---------------------------------------------------------------------------
// Scratch (device globals: allocation-free)
// ---------------------------------------------------------------------------
__device__ __half g_ft[(size_t)B_ * HP * WP * CIN];  // fp16 NHWC padded
__device__ __half g_w1h[9 * MID * CIN];              // fp16 [(dy*8+cc)*3+dx][mid][32]
__device__ __half g_w2h[80 * MID];                   // fp16 w2 padded to 80 rows
__device__ float  g_g[(size_t)B_ * Kk * HW * 4];     // guidance [b][k][hw][4]

// ---------------------------------------------------------------------------
// Helpers
// ---------------------------------------------------------------------------
static __device__ __forceinline__ unsigned smem_u32(const void* p) {
    unsigned r;
    asm("{ .reg .u64 t; cvta.to.shared.u64 t, %1; cvt.u32.u64 %0, t; }"
        : "=r"(r) : "l"(p));
    return r;
}

static __device__ __forceinline__ void cp16(unsigned saddr, const void* gptr) {
    asm volatile("cp.async.cg.shared.global [%0], [%1], 16;"
                 :: "r"(saddr), "l"(gptr));
}

static __device__ __forceinline__ void ldsm4(unsigned* r, unsigned addr) {
    asm volatile("ldmatrix.sync.aligned.m8n8.x4.shared.b16 {%0,%1,%2,%3}, [%4];"
        : "=r"(r[0]), "=r"(r[1]), "=r"(r[2]), "=r"(r[3]) : "r"(addr));
}

static __device__ __forceinline__ void mma16816(float* c, const unsigned* a,
                                                const unsigned* b) {
    asm volatile(
        "mma.sync.aligned.m16n8k16.row.col.f32.f16.f16.f32 "
        "{%0,%1,%2,%3}, {%4,%5,%6,%7}, {%8,%9}, {%0,%1,%2,%3};"
        : "+f"(c[0]), "+f"(c[1]), "+f"(c[2]), "+f"(c[3])
        : "r"(a[0]), "r"(a[1]), "r"(a[2]), "r"(a[3]), "r"(b[0]), "r"(b[1]));
}

// swizzled offset within a 64B-row tile
static __device__ __forceinline__ unsigned swz64(int row, int ch) {
    return row * 64 + ((ch ^ ((row >> 1) & 3)) << 4);
}
// swizzled offset within a 256B-row tile
static __device__ __forceinline__ unsigned swz256(int row, int ch) {
    return row * 256 + ((ch & 8) << 4) + (((ch & 7) ^ (row & 7)) << 4);
}

// ---------------------------------------------------------------------------
// Kernel T1: feats NCHW -> padded NHWC fp16. grid (HP, B), 256 threads.
// float4 reads, float4 (8xfp16) stores.
// ---------------------------------------------------------------------------
__global__ __launch_bounds__(256) void transpose_pad_kernel(
    const float* __restrict__ feats)
{
    __shared__ float s[32][133];
    const int tid = threadIdx.x;
    const int hp = blockIdx.x, b = blockIdx.y;
    __half* orow = g_ft + ((size_t)(b * HP + hp) * WP) * CIN;

    if (hp == 0 || hp == HP - 1) {
        uint4 z = make_uint4(0, 0, 0, 0);
        for (int i = tid; i < WP * CIN / 8; i += 256)
            *(uint4*)(orow + i * 8) = z;
        return;
    }
    orow[tid] = __float2half(0.f);
    orow[(WP - 1) * CIN + tid] = __float2half(0.f);

    const int h = hp - 1;
    for (int ws = 0; ws < 2; ws++) {
        const int w0 = ws * 128;
        for (int ct = 0; ct < 8; ct++) {
            const int c0 = ct * 32;
            __syncthreads();
#pragma unroll
            for (int i = 0; i < 4; i++) {
                int g = tid + i * 256;
                int ci = g >> 5, wq = g & 31;
                float4 v = *(const float4*)&feats[
                    (((size_t)b * CIN + c0 + ci) * Hh + h) * Ww + w0 + 4 * wq];
                s[ci][4 * wq]     = v.x;
                s[ci][4 * wq + 1] = v.y;
                s[ci][4 * wq + 2] = v.z;
                s[ci][4 * wq + 3] = v.w;
            }
            __syncthreads();
#pragma unroll
            for (int i = 0; i < 2; i++) {
                int g = tid + i * 256;
                int w = g >> 2, grp = g & 3;
                __half2 h4[4];
#pragma unroll
                for (int j = 0; j < 4; j++)
                    h4[j] = __floats2half2_rn(s[grp * 8 + 2 * j][w],
                                              s[grp * 8 + 2 * j + 1][w]);
                *(float4*)&orow[(size_t)(w0 + w + 1) * CIN + c0 + grp * 8] =
                    *(float4*)h4;
            }
        }
    }
}

// ---------------------------------------------------------------------------
// Kernel T2: both weight preps in one launch.
// ---------------------------------------------------------------------------
#define W1ELEMS (9 * MID * CIN)
__global__ __launch_bounds__(256) void prep_weights_kernel(
    const float* __restrict__ w1, const float* __restrict__ w2)
{
    int idx = blockIdx.x * 256 + threadIdx.x;
    if (idx < W1ELEMS) {
        int cw = idx & 31;
        int m  = (idx >> 5) & 127;
        int rest = idx >> 12;
        int dx = rest % 3, q = rest / 3;
        int cc = q & 7, dy = q >> 3;
        int ci = cc * 32 + cw;
        g_w1h[idx] = __float2half_rn(w1[(((size_t)m * CIN + ci) * 3 + dy) * 3 + dx]);
    } else if (idx < W1ELEMS + 80 * MID) {
        int j = idx - W1ELEMS;
        int n = j >> 7, m = j & 127;
        float v = (n < 76) ? w2[n * MID + m] : 0.f;
        g_w2h[j] = __float2half_rn(v);
    }
}

// ---------------------------------------------------------------------------
// Kernel G: conv3x3 fp16 mma implicit GEMM, 256 thr / 8 warps, 2 CTAs/SM.
// Per CTA one (b, h, half-row): M=128 px, N=128 mid, K=2304.
// FUSED epilogue: BN+ReLU -> smem x -> conv1x1 mma -> softmax -> g_g.
// (round-12 version — at the legacy-HMMA sustained-rate floor)
// ---------------------------------------------------------------------------
#define A_ST   8320                  // 130*64
#define B_ST   24576                 // 3*128*64
#define STG    (A_ST + B_ST)         // 32896
#define NSTG   3
#define CSMEM  (NSTG * STG)          // 98688; 2 CTAs = 197376
#define SX_OFF 0
#define SW2_OFF 32768

__global__ void __launch_bounds__(256, 2) conv3x3_fused_kernel(
    const float* __restrict__ gamma, const float* __restrict__ beta,
    const float* __restrict__ mean,  const float* __restrict__ var,
    const float* __restrict__ b2)
{
    extern __shared__ __align__(1024) unsigned char smem_raw[];
    const unsigned sbase = smem_u32(smem_raw);
    const int tid = threadIdx.x;
    const int L = tid & 31, wid = tid >> 5;
    const int h = blockIdx.x >> 1;
    const int wseg = (blockIdx.x & 1) * 128;
    const int b = blockIdx.y;
    const int p0w = (wid >> 2) * 64;
    const int n0w = (wid & 3) * 32;

    const int aL = L & 15, aH = L >> 4;
    const int bR = ((L >> 4) << 3) + (L & 7), bH = (L >> 3) & 1;

    auto issue_loads = [&](int t, int buf) {
        const int dy = t >> 3, cc = t & 7;
        const unsigned Ab = sbase + buf * STG;
        const unsigned Bb = Ab + A_ST;
        const __half* asrc = g_ft +
            ((size_t)(b * HP + h + dy) * WP + wseg) * CIN + cc * 32;
#pragma unroll
        for (int i = 0; i < 3; i++) {
            int g = tid + i * 256;
            if (g < 520) {
                int row = g >> 2, c = g & 3;
                cp16(Ab + swz64(row, c), asrc + (size_t)row * CIN + c * 8);
            }
        }
        const __half* bsrc = g_w1h + (size_t)((dy * 8 + cc) * 3) * MID * 32;
#pragma unroll
        for (int i = 0; i < 6; i++) {
            int g = tid + i * 256;
            int dxi = g >> 9, row = (g >> 2) & 127, c = g & 3;
            cp16(Bb + dxi * 8192 + swz64(row, c),
                 bsrc + (size_t)dxi * MID * 32 + row * 32 + c * 8);
        }
        asm volatile("cp.async.commit_group;");
    };

    float acc[4][4][4];
#pragma unroll
    for (int mi = 0; mi < 4; mi++)
#pragma unroll
        for (int ni = 0; ni < 4; ni++)
#pragma unroll
            for (int q = 0; q < 4; q++) acc[mi][ni][q] = 0.f;

    issue_loads(0, 0);
    issue_loads(1, 1);

    int buf = 0;
    for (int t = 0; t < 24; t++) {
        if (t < 23) asm volatile("cp.async.wait_group 1;");
        else        asm volatile("cp.async.wait_group 0;");
        __syncthreads();
        if (t < 22) {
            int nb = buf + 2; if (nb >= NSTG) nb -= NSTG;
            issue_loads(t + 2, nb);
        }
        const unsigned Ab = sbase + buf * STG;
        const unsigned Bb = Ab + A_ST;
#pragma unroll
        for (int dx = 0; dx < 3; dx++) {
#pragma unroll
            for (int kk = 0; kk < 2; kk++) {
                unsigned a[4][4], bf[2][4];
#pragma unroll
                for (int mi = 0; mi < 4; mi++) {
                    int row = p0w + mi * 16 + aL + dx;
                    ldsm4(a[mi], Ab + swz64(row, 2 * kk + aH));
                }
#pragma unroll
                for (int jj = 0; jj < 2; jj++) {
                    int row = n0w + jj * 16 + bR;
                    ldsm4(bf[jj], Bb + dx * 8192 + swz64(row, 2 * kk + bH));
                }
#pragma unroll
                for (int mi = 0; mi < 4; mi++)
#pragma unroll
                    for (int ni = 0; ni < 4; ni++)
                        mma16816(acc[mi][ni], a[mi],
                                 &bf[ni >> 1][(ni & 1) << 1]);
            }
        }
        buf++; if (buf >= NSTG) buf = 0;
    }
    __syncthreads();

    // ---- load w2 into smem (swz256) ----
    const unsigned sw2 = sbase + SW2_OFF;
#pragma unroll
    for (int i = 0; i < 5; i++) {
        int g = tid + i * 256;
        if (g < 1280) {
            int row = g >> 4, c = g & 15;
            cp16(sw2 + swz256(row, c), g_w2h + (size_t)row * MID + c * 8);
        }
    }
    asm volatile("cp.async.commit_group;");

    // ---- BN + ReLU, store x fp16 into smem ----
    const int midb = n0w + ((L & 3) << 1);
    {
        float iv0[4], iv1[4], bb0[4], bb1[4];
#pragma unroll
        for (int ni = 0; ni < 4; ni++) {
            int m0 = midb + ni * 8;
            iv0[ni] = gamma[m0]     * rsqrtf(var[m0]     + EPSBN);
            iv1[ni] = gamma[m0 + 1] * rsqrtf(var[m0 + 1] + EPSBN);
            bb0[ni] = beta[m0]     - mean[m0]     * iv0[ni];
            bb1[ni] = beta[m0 + 1] - mean[m0 + 1] * iv1[ni];
        }
        const int chb = (n0w >> 3);
        const int boff = (L & 3) * 4;
#pragma unroll
        for (int mi = 0; mi < 4; mi++) {
            int p0 = p0w + mi * 16 + (L >> 2);
#pragma unroll
            for (int ni = 0; ni < 4; ni++) {
                float u0 = fmaxf(fmaf(acc[mi][ni][0], iv0[ni], bb0[ni]), 0.f);
                float u1 = fmaxf(fmaf(acc[mi][ni][1], iv1[ni], bb1[ni]), 0.f);
                float u2 = fmaxf(fmaf(acc[mi][ni][2], iv0[ni], bb0[ni]), 0.f);
                float u3 = fmaxf(fmaf(acc[mi][ni][3], iv1[ni], bb1[ni]), 0.f);
                *(__half2*)(smem_raw + SX_OFF + swz256(p0, chb + ni) + boff)
                    = __floats2half2_rn(u0, u1);
                *(__half2*)(smem_raw + SX_OFF + swz256(p0 + 8, chb + ni) + boff)
                    = __floats2half2_rn(u2, u3);
            }
        }
    }
    asm volatile("cp.async.wait_group 0;");
    __syncthreads();

    // ---- conv1x1: per-warp 16px x 80n x 128k fp16 mma ----
    const unsigned sx = sbase + SX_OFF;
    const int pwm = wid * 16;
    float a1[10][4];
#pragma unroll
    for (int ni = 0; ni < 10; ni++)
#pragma unroll
        for (int q = 0; q < 4; q++) a1[ni][q] = 0.f;

#pragma unroll
    for (int kk = 0; kk < 8; kk++) {
        unsigned av[4], bf[5][4];
        {
            int row = pwm + (L & 15);
            ldsm4(av, sx + swz256(row, 2 * kk + (L >> 4)));
        }
#pragma unroll
        for (int jj = 0; jj < 5; jj++) {
            int row = jj * 16 + ((L >> 4) << 3) + (L & 7);
            ldsm4(bf[jj], sw2 + swz256(row, 2 * kk + ((L >> 3) & 1)));
        }
#pragma unroll
        for (int ni = 0; ni < 10; ni++)
            mma16816(a1[ni], av, &bf[ni >> 1][(ni & 1) << 1]);
    }

    // ---- bias + softmax over 4 dirs, write g_g ----
    const int d0 = (L & 1) * 2;
#pragma unroll
    for (int h2 = 0; h2 < 2; h2++) {
        int px = pwm + (L >> 2) + h2 * 8;
        size_t gp = (size_t)h * Ww + wseg + px;
#pragma unroll
        for (int ni = 0; ni < 10; ni++) {
            int n0 = 8 * ni + 2 * (L & 3);
            bool valid = (n0 < 76);
            float bb0 = valid ? b2[n0] : 0.f;
            float bb1 = valid ? b2[n0 + 1] : 0.f;
            float v0 = a1[ni][2 * h2]     + bb0;
            float v1 = a1[ni][2 * h2 + 1] + bb1;
            float p0v = __shfl_xor_sync(0xFFFFFFFFu, v0, 1);
            float p1v = __shfl_xor_sync(0xFFFFFFFFu, v1, 1);
            float mx = fmaxf(fmaxf(v0, v1), fmaxf(p0v, p1v));
            float e0 = expf(v0 - mx), e1 = expf(v1 - mx);
            float ep0 = expf(p0v - mx), ep1 = expf(p1v - mx);
            float inv = 1.f / (e0 + e1 + ep0 + ep1);
            if (valid) {
                int k = n0 >> 2;
                float2 r; r.x = e0 * inv; r.y = e1 * inv;
                *(float2*)(g_g + (((size_t)b * Kk + k) * HW + gp) * 4 + d0) = r;
            }
        }
    }
}

// ---------------------------------------------------------------------------
// Kernel 3: 4 fused propagation steps; 32x32 tile + halo 4.
// VECTORIZED: each thread owns up to 2 row-strips of 4 cells; g in registers;
// per strip per step: 3x LDS.128 + <=2 scalar LDS + 1x STS.128.
// ---------------------------------------------------------------------------
#define TR 40
#define NSTRIP 400                  // 40 rows x 10 strips

__global__ __launch_bounds__(256) void prop_fused_kernel(
    const float* __restrict__ logits, float* __restrict__ h_out)
{
    __shared__ float sh[2][TR * TR];

    const int tid = threadIdx.x;
    const int wo = blockIdx.x * 32, ho = blockIdx.y * 32;
    const int plane = blockIdx.z;
    const float* hsrc = logits + (size_t)plane * HW;
    const float* gsrc = g_g + (size_t)plane * HW * 4;

    float4 gr[2][4];
    int srow[2], scol[2];
    bool owns[2];

#pragma unroll
    for (int i = 0; i < 2; i++) {
        int s = tid + i * 256;
        owns[i] = (s < NSTRIP);
        int r = 0, c0 = 0;
        if (owns[i]) { r = s / 10; c0 = (s - r * 10) * 4; }
        srow[i] = r; scol[i] = c0;
        float hv[4];
#pragma unroll
        for (int j = 0; j < 4; j++) {
            float4 gv = make_float4(0.f, 0.f, 0.f, 0.f);
            float hx = 0.f;
            if (owns[i]) {
                int grow = ho + r - 4, gcol = wo + c0 + j - 4;
                bool in = ((unsigned)grow < (unsigned)Hh) &&
                          ((unsigned)gcol < (unsigned)Ww);
                if (in) {
                    gv = *(const float4*)(gsrc + ((size_t)grow * Ww + gcol) * 4);
                    hx = hsrc[(size_t)grow * Ww + gcol];
                }
            }
            gr[i][j] = gv;
            hv[j] = hx;
        }
        if (owns[i])
            *(float4*)&sh[0][r * TR + c0] = make_float4(hv[0], hv[1], hv[2], hv[3]);
    }
    __syncthreads();

    // steps 1..3 in smem ping-pong
#pragma unroll
    for (int st = 1; st <= 3; st++) {
        const float* src = sh[(st - 1) & 1];
        float* dst = sh[st & 1];
#pragma unroll
        for (int i = 0; i < 2; i++) {
            if (!owns[i]) continue;
            const int r = srow[i], c0 = scol[i];
            if (r < st || r >= TR - st) continue;
            const int cl = (c0 > st) ? c0 : st;
            const int cr = (c0 + 4 < TR - st) ? (c0 + 4) : (TR - st);
            if (cl >= cr) continue;
            const int base = r * TR + c0;
            float4 hc = *(const float4*)&src[base];
            float4 u4 = *(const float4*)&src[base - TR];
            float4 d4 = *(const float4*)&src[base + TR];
            float lsc = (cl == c0) ? src[base - 1] : 0.f;
            float rsc = (cr == c0 + 4) ? src[base + 4] : 0.f;
            float hcA[4] = {hc.x, hc.y, hc.z, hc.w};
            float uA[4]  = {u4.x, u4.y, u4.z, u4.w};
            float dA[4]  = {d4.x, d4.y, d4.z, d4.w};
            float res[4];
#pragma unroll
            for (int j = 0; j < 4; j++) {
                float l  = (j == 0) ? lsc : hcA[j - 1];
                float rt = (j == 3) ? rsc : hcA[j + 1];
                float4 gv = gr[i][j];
                float selfw = 1.f - (gv.x + gv.y + gv.z + gv.w);
                res[j] = selfw * hcA[j] + gv.x * l + gv.y * rt
                       + gv.z * uA[j] + gv.w * dA[j];
            }
            if (cl == c0 && cr == c0 + 4) {
                *(float4*)&dst[base] = make_float4(res[0], res[1], res[2], res[3]);
            } else {
#pragma unroll
                for (int j = 0; j < 4; j++)
                    if (c0 + j >= cl && c0 + j < cr) dst[base + j] = res[j];
            }
        }
        __syncthreads();
    }

    // step 4: interior 32x32 -> gmem
    const float* src = sh[1];
#pragma unroll
    for (int i = 0; i < 2; i++) {
        if (!owns[i]) continue;
        const int r = srow[i], c0 = scol[i];
        if (r < 4 || r >= TR - 4) continue;
        const int cl = (c0 > 4) ? c0 : 4;
        const int cr = (c0 + 4 < TR - 4) ? (c0 + 4) : (TR - 4);
        if (cl >= cr) continue;
        const int base = r * TR + c0;
        float4 hc = *(const float4*)&src[base];
        float4 u4 = *(const float4*)&src[base - TR];
        float4 d4 = *(const float4*)&src[base + TR];
        float lsc = (cl == c0) ? src[base - 1] : 0.f;
        float rsc = (cr == c0 + 4) ? src[base + 4] : 0.f;
        float hcA[4] = {hc.x, hc.y, hc.z, hc.w};
        float uA[4]  = {u4.x, u4.y, u4.z, u4.w};
        float dA[4]  = {d4.x, d4.y, d4.z, d4.w};
        float res[4];
#pragma unroll
        for (int j = 0; j < 4; j++) {
            float l  = (j == 0) ? lsc : hcA[j - 1];
            float rt = (j == 3) ? rsc : hcA[j + 1];
            float4 gv = gr[i][j];
            float selfw = 1.f - (gv.x + gv.y + gv.z + gv.w);
            res[j] = selfw * hcA[j] + gv.x * l + gv.y * rt
                   + gv.z * uA[j] + gv.w * dA[j];
        }
        float* op = h_out + (size_t)plane * HW
                  + (size_t)(ho + r - 4) * Ww + (wo + c0 - 4);
        if (cl == c0 && cr == c0 + 4) {
            *(float4*)op = make_float4(res[0], res[1], res[2], res[3]);
        } else {
#pragma unroll
            for (int j = 0; j < 4; j++)
                if (c0 + j >= cl && c0 + j < cr) op[j] = res[j];
        }
    }
}

// ---------------------------------------------------------------------------
// kernel_launch
// inputs: 0 feats, 1 logits, 2 w1, 3 gamma, 4 beta, 5 mean, 6 var, 7 w2, 8 b2
// ---------------------------------------------------------------------------
extern "C" void kernel_launch(void* const* d_in, const int* in_sizes, int n_in,
                              void* d_out, int out_size)
{
    const float* feats  = (const float*)d_in[0];
    const float* logits = (const float*)d_in[1];
    const float* w1     = (const float*)d_in[2];
    const float* gamma  = (const float*)d_in[3];
    const float* beta   = (const float*)d_in[4];
    const float* mean   = (const float*)d_in[5];
    const float* var    = (const float*)d_in[6];
    const float* w2     = (const float*)d_in[7];
    const float* b2     = (const float*)d_in[8];
    float* out = (float*)d_out;

    cudaFuncSetAttribute(conv3x3_fused_kernel,
                         cudaFuncAttributeMaxDynamicSharedMemorySize, CSMEM);

    prep_weights_kernel<<<(W1ELEMS + 80 * MID + 255) / 256, 256>>>(w1, w2);
    transpose_pad_kernel<<<dim3(HP, B_), 256>>>(feats);
    conv3x3_fused_kernel<<<dim3(Hh * 2, B_), 256, CSMEM>>>(
        gamma, beta, mean, var, b2);
    prop_fused_kernel<<<dim3(Ww / 32, Hh / 32, B_ * Kk), 256>>>(logits, out);
}

// round 15
// speedup vs baseline: 1.0805x; 1.0317x over previous
#include <cuda_runtime.h>
#include <cuda_fp16.h>
#include <math.h>

// ---------------------------------------------------------------------------
// Problem constants
// ---------------------------------------------------------------------------
#define B_    8
#define CIN   256
#define MID   128
#define Hh    128
#define Ww    256
#define Kk    19
#define HW    (Hh*Ww)          // 32768
#define EPSBN 1e-5f
#define HP    (Hh+2)           // 130
#define WP    (Ww+2)           // 258

// ---------------------------------------------------------------------------
// Scratch (device globals: allocation-free)
// ---------------------------------------------------------------------------
__device__ __half g_ft[(size_t)B_ * HP * WP * CIN];  // fp16 NHWC padded
__device__ __half g_w1h[9 * MID * CIN];              // fp16 [(dy*8+cc)*3+dx][mid][32]
__device__ __half g_w2h[80 * MID];                   // fp16 w2 padded to 80 rows
__device__ float  g_g[(size_t)B_ * Kk * HW * 4];     // guidance [b][k][hw][4]

// ---------------------------------------------------------------------------
// Helpers
// ---------------------------------------------------------------------------
static __device__ __forceinline__ unsigned smem_u32(const void* p) {
    unsigned r;
    asm("{ .reg .u64 t; cvta.to.shared.u64 t, %1; cvt.u32.u64 %0, t; }"
        : "=r"(r) : "l"(p));
    return r;
}

static __device__ __forceinline__ void cp16(unsigned saddr, const void* gptr) {
    asm volatile("cp.async.cg.shared.global [%0], [%1], 16;"
                 :: "r"(saddr), "l"(gptr));
}

static __device__ __forceinline__ void ldsm4(unsigned* r, unsigned addr) {
    asm volatile("ldmatrix.sync.aligned.m8n8.x4.shared.b16 {%0,%1,%2,%3}, [%4];"
        : "=r"(r[0]), "=r"(r[1]), "=r"(r[2]), "=r"(r[3]) : "r"(addr));
}

static __device__ __forceinline__ void mma16816(float* c, const unsigned* a,
                                                const unsigned* b) {
    asm volatile(
        "mma.sync.aligned.m16n8k16.row.col.f32.f16.f16.f32 "
        "{%0,%1,%2,%3}, {%4,%5,%6,%7}, {%8,%9}, {%0,%1,%2,%3};"
        : "+f"(c[0]), "+f"(c[1]), "+f"(c[2]), "+f"(c[3])
        : "r"(a[0]), "r"(a[1]), "r"(a[2]), "r"(a[3]), "r"(b[0]), "r"(b[1]));
}

// swizzled offset within a 64B-row tile
static __device__ __forceinline__ unsigned swz64(int row, int ch) {
    return row * 64 + ((ch ^ ((row >> 1) & 3)) << 4);
}
// swizzled offset within a 256B-row tile
static __device__ __forceinline__ unsigned swz256(int row, int ch) {
    return row * 256 + ((ch & 8) << 4) + (((ch & 7) ^ (row & 7)) << 4);
}

// ---------------------------------------------------------------------------
// Kernel T1: feats NCHW -> padded NHWC fp16 + weight prep, ONE launch.
// 1D grid: blocks [0, HP*B) transpose; blocks >= HP*B do weight prep.
// ---------------------------------------------------------------------------
#define TBLOCKS (HP * B_)            // 1040
#define W1ELEMS (9 * MID * CIN)      // 294912
#define PREPTOT (W1ELEMS + 80 * MID) // 305152
#define PREPBLK ((PREPTOT + 255) / 256)  // 1193

__global__ __launch_bounds__(256) void transpose_prep_kernel(
    const float* __restrict__ feats,
    const float* __restrict__ w1, const float* __restrict__ w2)
{
    const int tid = threadIdx.x;

    if (blockIdx.x >= TBLOCKS) {
        // ---- weight prep ----
        int idx = (blockIdx.x - TBLOCKS) * 256 + tid;
        if (idx < W1ELEMS) {
            int cw = idx & 31;
            int m  = (idx >> 5) & 127;
            int rest = idx >> 12;
            int dx = rest % 3, q = rest / 3;
            int cc = q & 7, dy = q >> 3;
            int ci = cc * 32 + cw;
            g_w1h[idx] = __float2half_rn(
                w1[(((size_t)m * CIN + ci) * 3 + dy) * 3 + dx]);
        } else if (idx < PREPTOT) {
            int j = idx - W1ELEMS;
            int n = j >> 7, m = j & 127;
            float v = (n < 76) ? w2[n * MID + m] : 0.f;
            g_w2h[j] = __float2half_rn(v);
        }
        return;
    }

    // ---- transpose ----
    __shared__ float s[32][133];
    const int hp = blockIdx.x % HP, b = blockIdx.x / HP;
    __half* orow = g_ft + ((size_t)(b * HP + hp) * WP) * CIN;

    if (hp == 0 || hp == HP - 1) {
        uint4 z = make_uint4(0, 0, 0, 0);
        for (int i = tid; i < WP * CIN / 8; i += 256)
            *(uint4*)(orow + i * 8) = z;
        return;
    }
    orow[tid] = __float2half(0.f);
    orow[(WP - 1) * CIN + tid] = __float2half(0.f);

    const int h = hp - 1;
    for (int ws = 0; ws < 2; ws++) {
        const int w0 = ws * 128;
        for (int ct = 0; ct < 8; ct++) {
            const int c0 = ct * 32;
            __syncthreads();
#pragma unroll
            for (int i = 0; i < 4; i++) {
                int g = tid + i * 256;
                int ci = g >> 5, wq = g & 31;
                float4 v = *(const float4*)&feats[
                    (((size_t)b * CIN + c0 + ci) * Hh + h) * Ww + w0 + 4 * wq];
                s[ci][4 * wq]     = v.x;
                s[ci][4 * wq + 1] = v.y;
                s[ci][4 * wq + 2] = v.z;
                s[ci][4 * wq + 3] = v.w;
            }
            __syncthreads();
#pragma unroll
            for (int i = 0; i < 2; i++) {
                int g = tid + i * 256;
                int w = g >> 2, grp = g & 3;
                __half2 h4[4];
#pragma unroll
                for (int j = 0; j < 4; j++)
                    h4[j] = __floats2half2_rn(s[grp * 8 + 2 * j][w],
                                              s[grp * 8 + 2 * j + 1][w]);
                *(float4*)&orow[(size_t)(w0 + w + 1) * CIN + c0 + grp * 8] =
                    *(float4*)h4;
            }
        }
    }
}

// ---------------------------------------------------------------------------
// Kernel G: conv3x3 fp16 mma implicit GEMM, 256 thr / 8 warps, 2 CTAs/SM.
// Per CTA one (b, h, half-row): M=128 px, N=128 mid, K=2304.
// FUSED epilogue: BN+ReLU -> smem x -> conv1x1 mma -> softmax -> g_g.
// (round-12 version — at the legacy-HMMA sustained-rate floor)
// ---------------------------------------------------------------------------
#define A_ST   8320                  // 130*64
#define B_ST   24576                 // 3*128*64
#define STG    (A_ST + B_ST)         // 32896
#define NSTG   3
#define CSMEM  (NSTG * STG)          // 98688; 2 CTAs = 197376
#define SX_OFF 0
#define SW2_OFF 32768

__global__ void __launch_bounds__(256, 2) conv3x3_fused_kernel(
    const float* __restrict__ gamma, const float* __restrict__ beta,
    const float* __restrict__ mean,  const float* __restrict__ var,
    const float* __restrict__ b2)
{
    extern __shared__ __align__(1024) unsigned char smem_raw[];
    const unsigned sbase = smem_u32(smem_raw);
    const int tid = threadIdx.x;
    const int L = tid & 31, wid = tid >> 5;
    const int h = blockIdx.x >> 1;
    const int wseg = (blockIdx.x & 1) * 128;
    const int b = blockIdx.y;
    const int p0w = (wid >> 2) * 64;
    const int n0w = (wid & 3) * 32;

    const int aL = L & 15, aH = L >> 4;
    const int bR = ((L >> 4) << 3) + (L & 7), bH = (L >> 3) & 1;

    auto issue_loads = [&](int t, int buf) {
        const int dy = t >> 3, cc = t & 7;
        const unsigned Ab = sbase + buf * STG;
        const unsigned Bb = Ab + A_ST;
        const __half* asrc = g_ft +
            ((size_t)(b * HP + h + dy) * WP + wseg) * CIN + cc * 32;
#pragma unroll
        for (int i = 0; i < 3; i++) {
            int g = tid + i * 256;
            if (g < 520) {
                int row = g >> 2, c = g & 3;
                cp16(Ab + swz64(row, c), asrc + (size_t)row * CIN + c * 8);
            }
        }
        const __half* bsrc = g_w1h + (size_t)((dy * 8 + cc) * 3) * MID * 32;
#pragma unroll
        for (int i = 0; i < 6; i++) {
            int g = tid + i * 256;
            int dxi = g >> 9, row = (g >> 2) & 127, c = g & 3;
            cp16(Bb + dxi * 8192 + swz64(row, c),
                 bsrc + (size_t)dxi * MID * 32 + row * 32 + c * 8);
        }
        asm volatile("cp.async.commit_group;");
    };

    float acc[4][4][4];
#pragma unroll
    for (int mi = 0; mi < 4; mi++)
#pragma unroll
        for (int ni = 0; ni < 4; ni++)
#pragma unroll
            for (int q = 0; q < 4; q++) acc[mi][ni][q] = 0.f;

    issue_loads(0, 0);
    issue_loads(1, 1);

    int buf = 0;
    for (int t = 0; t < 24; t++) {
        if (t < 23) asm volatile("cp.async.wait_group 1;");
        else        asm volatile("cp.async.wait_group 0;");
        __syncthreads();
        if (t < 22) {
            int nb = buf + 2; if (nb >= NSTG) nb -= NSTG;
            issue_loads(t + 2, nb);
        }
        const unsigned Ab = sbase + buf * STG;
        const unsigned Bb = Ab + A_ST;
#pragma unroll
        for (int dx = 0; dx < 3; dx++) {
#pragma unroll
            for (int kk = 0; kk < 2; kk++) {
                unsigned a[4][4], bf[2][4];
#pragma unroll
                for (int mi = 0; mi < 4; mi++) {
                    int row = p0w + mi * 16 + aL + dx;
                    ldsm4(a[mi], Ab + swz64(row, 2 * kk + aH));
                }
#pragma unroll
                for (int jj = 0; jj < 2; jj++) {
                    int row = n0w + jj * 16 + bR;
                    ldsm4(bf[jj], Bb + dx * 8192 + swz64(row, 2 * kk + bH));
                }
#pragma unroll
                for (int mi = 0; mi < 4; mi++)
#pragma unroll
                    for (int ni = 0; ni < 4; ni++)
                        mma16816(acc[mi][ni], a[mi],
                                 &bf[ni >> 1][(ni & 1) << 1]);
            }
        }
        buf++; if (buf >= NSTG) buf = 0;
    }
    __syncthreads();

    // ---- load w2 into smem (swz256) ----
    const unsigned sw2 = sbase + SW2_OFF;
#pragma unroll
    for (int i = 0; i < 5; i++) {
        int g = tid + i * 256;
        if (g < 1280) {
            int row = g >> 4, c = g & 15;
            cp16(sw2 + swz256(row, c), g_w2h + (size_t)row * MID + c * 8);
        }
    }
    asm volatile("cp.async.commit_group;");

    // ---- BN + ReLU, store x fp16 into smem ----
    const int midb = n0w + ((L & 3) << 1);
    {
        float iv0[4], iv1[4], bb0[4], bb1[4];
#pragma unroll
        for (int ni = 0; ni < 4; ni++) {
            int m0 = midb + ni * 8;
            iv0[ni] = gamma[m0]     * rsqrtf(var[m0]     + EPSBN);
            iv1[ni] = gamma[m0 + 1] * rsqrtf(var[m0 + 1] + EPSBN);
            bb0[ni] = beta[m0]     - mean[m0]     * iv0[ni];
            bb1[ni] = beta[m0 + 1] - mean[m0 + 1] * iv1[ni];
        }
        const int chb = (n0w >> 3);
        const int boff = (L & 3) * 4;
#pragma unroll
        for (int mi = 0; mi < 4; mi++) {
            int p0 = p0w + mi * 16 + (L >> 2);
#pragma unroll
            for (int ni = 0; ni < 4; ni++) {
                float u0 = fmaxf(fmaf(acc[mi][ni][0], iv0[ni], bb0[ni]), 0.f);
                float u1 = fmaxf(fmaf(acc[mi][ni][1], iv1[ni], bb1[ni]), 0.f);
                float u2 = fmaxf(fmaf(acc[mi][ni][2], iv0[ni], bb0[ni]), 0.f);
                float u3 = fmaxf(fmaf(acc[mi][ni][3], iv1[ni], bb1[ni]), 0.f);
                *(__half2*)(smem_raw + SX_OFF + swz256(p0, chb + ni) + boff)
                    = __floats2half2_rn(u0, u1);
                *(__half2*)(smem_raw + SX_OFF + swz256(p0 + 8, chb + ni) + boff)
                    = __floats2half2_rn(u2, u3);
            }
        }
    }
    asm volatile("cp.async.wait_group 0;");
    __syncthreads();

    // ---- conv1x1: per-warp 16px x 80n x 128k fp16 mma ----
    const unsigned sx = sbase + SX_OFF;
    const int pwm = wid * 16;
    float a1[10][4];
#pragma unroll
    for (int ni = 0; ni < 10; ni++)
#pragma unroll
        for (int q = 0; q < 4; q++) a1[ni][q] = 0.f;

#pragma unroll
    for (int kk = 0; kk < 8; kk++) {
        unsigned av[4], bf[5][4];
        {
            int row = pwm + (L & 15);
            ldsm4(av, sx + swz256(row, 2 * kk + (L >> 4)));
        }
#pragma unroll
        for (int jj = 0; jj < 5; jj++) {
            int row = jj * 16 + ((L >> 4) << 3) + (L & 7);
            ldsm4(bf[jj], sw2 + swz256(row, 2 * kk + ((L >> 3) & 1)));
        }
#pragma unroll
        for (int ni = 0; ni < 10; ni++)
            mma16816(a1[ni], av, &bf[ni >> 1][(ni & 1) << 1]);
    }

    // ---- bias + softmax over 4 dirs, write g_g ----
    const int d0 = (L & 1) * 2;
#pragma unroll
    for (int h2 = 0; h2 < 2; h2++) {
        int px = pwm + (L >> 2) + h2 * 8;
        size_t gp = (size_t)h * Ww + wseg + px;
#pragma unroll
        for (int ni = 0; ni < 10; ni++) {
            int n0 = 8 * ni + 2 * (L & 3);
            bool valid = (n0 < 76);
            float bb0 = valid ? b2[n0] : 0.f;
            float bb1 = valid ? b2[n0 + 1] : 0.f;
            float v0 = a1[ni][2 * h2]     + bb0;
            float v1 = a1[ni][2 * h2 + 1] + bb1;
            float p0v = __shfl_xor_sync(0xFFFFFFFFu, v0, 1);
            float p1v = __shfl_xor_sync(0xFFFFFFFFu, v1, 1);
            float mx = fmaxf(fmaxf(v0, v1), fmaxf(p0v, p1v));
            float e0 = expf(v0 - mx), e1 = expf(v1 - mx);
            float ep0 = expf(p0v - mx), ep1 = expf(p1v - mx);
            float inv = 1.f / (e0 + e1 + ep0 + ep1);
            if (valid) {
                int k = n0 >> 2;
                float2 r; r.x = e0 * inv; r.y = e1 * inv;
                *(float2*)(g_g + (((size_t)b * Kk + k) * HW + gp) * 4 + d0) = r;
            }
        }
    }
}

// ---------------------------------------------------------------------------
// Kernel 3: 4 fused propagation steps; 32x32 tile + halo 4 (round-10 best).
// g cached in registers (step-invariant), 7 cells/thread, scalar LDS/STS.
// ---------------------------------------------------------------------------
#define TR 40
#define NCELL 7

__global__ __launch_bounds__(256) void prop_fused_kernel(
    const float* __restrict__ logits, float* __restrict__ h_out)
{
    __shared__ float sh[2][TR * TR];

    const int tid = threadIdx.x;
    const int wo = blockIdx.x * 32, ho = blockIdx.y * 32;
    const int plane = blockIdx.z;
    const float* hsrc = logits + (size_t)plane * HW;
    const float* gsrc = g_g + (size_t)plane * HW * 4;

    float4 gr[NCELL];
    int rr_[NCELL], cc_[NCELL];
    bool own[NCELL];

#pragma unroll
    for (int i = 0; i < NCELL; i++) {
        int q = tid + i * 256;
        own[i] = (q < TR * TR);
        int r = q / TR, c = q - r * TR;
        rr_[i] = r; cc_[i] = c;
        float4 gv = make_float4(0.f, 0.f, 0.f, 0.f);
        float hv = 0.f;
        if (own[i]) {
            int grow = ho + r - 4, gcol = wo + c - 4;
            bool in = ((unsigned)grow < (unsigned)Hh) &&
                      ((unsigned)gcol < (unsigned)Ww);
            if (in) {
                gv = *(const float4*)(gsrc + ((size_t)grow * Ww + gcol) * 4);
                hv = hsrc[(size_t)grow * Ww + gcol];
            }
            sh[0][q] = hv;
        }
        gr[i] = gv;
    }
    __syncthreads();

#pragma unroll
    for (int s = 1; s <= 3; s++) {
        const float* src = sh[(s - 1) & 1];
        float* dst = sh[s & 1];
#pragma unroll
        for (int i = 0; i < NCELL; i++) {
            if (!own[i]) continue;
            int r = rr_[i], c = cc_[i];
            if (r >= s && r < TR - s && c >= s && c < TR - s) {
                int id = r * TR + c;
                float hc = src[id];
                float l = src[id - 1], rt = src[id + 1];
                float u = src[id - TR], d = src[id + TR];
                float4 gv = gr[i];
                float selfw = 1.f - (gv.x + gv.y + gv.z + gv.w);
                dst[id] = selfw * hc + gv.x * l + gv.y * rt + gv.z * u + gv.w * d;
            }
        }
        __syncthreads();
    }

    const float* src = sh[1];
#pragma unroll
    for (int i = 0; i < NCELL; i++) {
        if (!own[i]) continue;
        int r = rr_[i], c = cc_[i];
        if (r >= 4 && r < TR - 4 && c >= 4 && c < TR - 4) {
            int id = r * TR + c;
            float hc = src[id];
            float l = src[id - 1], rt = src[id + 1];
            float u = src[id - TR], d = src[id + TR];
            float4 gv = gr[i];
            float selfw = 1.f - (gv.x + gv.y + gv.z + gv.w);
            float res = selfw * hc + gv.x * l + gv.y * rt + gv.z * u + gv.w * d;
            h_out[(size_t)plane * HW + (size_t)(ho + r - 4) * Ww + (wo + c - 4)] = res;
        }
    }
}

// ---------------------------------------------------------------------------
// kernel_launch
// inputs: 0 feats, 1 logits, 2 w1, 3 gamma, 4 beta, 5 mean, 6 var, 7 w2, 8 b2
// ---------------------------------------------------------------------------
extern "C" void kernel_launch(void* const* d_in, const int* in_sizes, int n_in,
                              void* d_out, int out_size)
{
    const float* feats  = (const float*)d_in[0];
    const float* logits = (const float*)d_in[1];
    const float* w1     = (const float*)d_in[2];
    const float* gamma  = (const float*)d_in[3];
    const float* beta   = (const float*)d_in[4];
    const float* mean   = (const float*)d_in[5];
    const float* var    = (const float*)d_in[6];
    const float* w2     = (const float*)d_in[7];
    const float* b2     = (const float*)d_in[8];
    float* out = (float*)d_out;

    cudaFuncSetAttribute(conv3x3_fused_kernel,
                         cudaFuncAttributeMaxDynamicSharedMemorySize, CSMEM);

    transpose_prep_kernel<<<TBLOCKS + PREPBLK, 256>>>(feats, w1, w2);
    conv3x3_fused_kernel<<<dim3(Hh * 2, B_), 256, CSMEM>>>(
        gamma, beta, mean, var, b2);
    prop_fused_kernel<<<dim3(Ww / 32, Hh / 32, B_ * Kk), 256>>>(logits, out);
}